// round 2
// baseline (speedup 1.0000x reference)
#include <cuda_runtime.h>

// Problem constants
#define M_DIM   16
#define DICT    64
#define N_DIM   8
#define B_DIM   8192
#define KTERMS  24
#define BDIM    256

typedef unsigned long long u64;

// Duplicated 1/k table (both f32 lanes equal), k=0 unused
#define IK(k) {1.0f/(k), 1.0f/(k)}
__device__ __constant__ float2 INVK2[KTERMS + 1] = {
    {0.f, 0.f},
    IK(1),  IK(2),  IK(3),  IK(4),  IK(5),  IK(6),  IK(7),  IK(8),
    IK(9),  IK(10), IK(11), IK(12), IK(13), IK(14), IK(15), IK(16),
    IK(17), IK(18), IK(19), IK(20), IK(21), IK(22), IK(23), IK(24)
};

// ---- packed f32x2 helpers (ptxas never emits FFMA2 from C++) ----
__device__ __forceinline__ u64 fma2(u64 a, u64 b, u64 c) {
    u64 d; asm("fma.rn.f32x2 %0, %1, %2, %3;" : "=l"(d) : "l"(a), "l"(b), "l"(c)); return d;
}
__device__ __forceinline__ u64 mul2(u64 a, u64 b) {
    u64 d; asm("mul.rn.f32x2 %0, %1, %2;" : "=l"(d) : "l"(a), "l"(b)); return d;
}
__device__ __forceinline__ u64 dup2(float v) {
    u64 r; asm("mov.b64 %0, {%1, %1};" : "=l"(r) : "f"(v)); return r;
}
__device__ __forceinline__ u64 pack2(float lo, float hi) {
    u64 r; asm("mov.b64 %0, {%1, %2};" : "=l"(r) : "f"(lo), "f"(hi)); return r;
}
__device__ __forceinline__ void unpack2(u64 v, float& lo, float& hi) {
    asm("mov.b64 {%0, %1}, %2;" : "=f"(lo), "=f"(hi) : "l"(v));
}

// Grid: (B/256, DICT). One block = 256 consecutive b for one dictionary slot s.
// Per thread: build packed 8x8 A (row-pairs), 24-term Taylor expm(A)*x, all f32x2.
__global__ __launch_bounds__(BDIM, 2)
void transop_expm_kernel(const float* __restrict__ x,
                         const float* __restrict__ c,
                         const float* __restrict__ psi,
                         float* __restrict__ out)
{
    const int s = blockIdx.y;
    const int b = blockIdx.x * BDIM + threadIdx.x;

    // Packed psi slice: float2 pair (psi[m][2p][j], psi[m][2p+1][j]) at
    // float2 index m*32 + p*8 + j.  16B-aligned for LDS.128.
    __shared__ ulonglong2 psiP2[M_DIM * 16];   // 4 KB
    {
        float2* psiPf = reinterpret_cast<float2*>(psiP2);
        const int t = threadIdx.x;
        #pragma unroll
        for (int u = 0; u < 2; u++) {
            int i = t + u * BDIM;          // 0..511
            int m = i >> 5;
            int r = i & 31;
            int p = r >> 3;
            int j = r & 7;
            const float* base = psi + ((m * DICT + s) << 6);
            psiPf[i] = make_float2(base[16 * p + j], base[16 * p + j + 8]);
        }
    }
    __syncthreads();

    // c[b, :] — 16 contiguous floats
    float cm[M_DIM];
    {
        const float4* c4 = reinterpret_cast<const float4*>(c + (size_t)b * M_DIM);
        float4 c0 = c4[0], c1 = c4[1], c2 = c4[2], c3 = c4[3];
        cm[0] = c0.x; cm[1] = c0.y; cm[2]  = c0.z; cm[3]  = c0.w;
        cm[4] = c1.x; cm[5] = c1.y; cm[6]  = c1.z; cm[7]  = c1.w;
        cm[8] = c2.x; cm[9] = c2.y; cm[10] = c2.z; cm[11] = c2.w;
        cm[12]= c3.x; cm[13]= c3.y; cm[14] = c3.z; cm[15] = c3.w;
    }

    // Ap[p*8+j] = packed (A[2p][j], A[2p+1][j])
    u64 Ap[32];
    #pragma unroll
    for (int i = 0; i < 32; i++) Ap[i] = 0ull;

    #pragma unroll
    for (int m = 0; m < M_DIM; m++) {
        const u64 cv2 = dup2(cm[m]);
        #pragma unroll
        for (int p = 0; p < 4; p++) {
            #pragma unroll
            for (int q = 0; q < 4; q++) {
                ulonglong2 w = psiP2[m * 16 + p * 4 + q];       // LDS.128 broadcast
                Ap[p * 8 + 2 * q]     = fma2(w.x, cv2, Ap[p * 8 + 2 * q]);
                Ap[p * 8 + 2 * q + 1] = fma2(w.y, cv2, Ap[p * 8 + 2 * q + 1]);
            }
        }
    }

    // x block + init: vdup[j] = (x_j, x_j); accp[p] = (x_2p, x_2p+1)
    u64 vdup[N_DIM], accp[4];
    {
        const float4* xp = reinterpret_cast<const float4*>(
            x + (size_t)b * (DICT * N_DIM) + s * N_DIM);
        float4 x0 = xp[0], x1 = xp[1];
        float xs[N_DIM] = {x0.x, x0.y, x0.z, x0.w, x1.x, x1.y, x1.z, x1.w};
        #pragma unroll
        for (int j = 0; j < N_DIM; j++) vdup[j] = dup2(xs[j]);
        #pragma unroll
        for (int p = 0; p < 4; p++) accp[p] = pack2(xs[2 * p], xs[2 * p + 1]);
    }

    // Taylor: acc = sum_k A^k x / k!    (all packed over row pairs)
    #pragma unroll 1
    for (int k = 1; k <= KTERMS; k++) {
        u64 tp[4];
        #pragma unroll
        for (int p = 0; p < 4; p++) {
            u64 sum = mul2(Ap[p * 8 + 0], vdup[0]);
            #pragma unroll
            for (int j = 1; j < N_DIM; j++)
                sum = fma2(Ap[p * 8 + j], vdup[j], sum);
            tp[p] = sum;
        }
        const u64 ik2 = *reinterpret_cast<const u64*>(&INVK2[k]);
        #pragma unroll
        for (int p = 0; p < 4; p++) {
            accp[p] = fma2(tp[p], ik2, accp[p]);
            u64 sv = mul2(tp[p], ik2);
            float lo, hi; unpack2(sv, lo, hi);
            vdup[2 * p]     = dup2(lo);
            vdup[2 * p + 1] = dup2(hi);
        }
    }

    // Store out[b, s*8 .. s*8+8)
    {
        float r0, r1, r2, r3, r4, r5, r6, r7;
        unpack2(accp[0], r0, r1);
        unpack2(accp[1], r2, r3);
        unpack2(accp[2], r4, r5);
        unpack2(accp[3], r6, r7);
        float4* op = reinterpret_cast<float4*>(
            out + (size_t)b * (DICT * N_DIM) + s * N_DIM);
        op[0] = make_float4(r0, r1, r2, r3);
        op[1] = make_float4(r4, r5, r6, r7);
    }
}

extern "C" void kernel_launch(void* const* d_in, const int* in_sizes, int n_in,
                              void* d_out, int out_size)
{
    const float* x   = (const float*)d_in[0];  // (8192, 512)
    const float* c   = (const float*)d_in[1];  // (8192, 16)
    const float* psi = (const float*)d_in[2];  // (16, 64, 8, 8)
    float* out = (float*)d_out;                // (8192, 512)

    dim3 grid(B_DIM / BDIM, DICT);
    transop_expm_kernel<<<grid, BDIM>>>(x, c, psi, out);
}